// round 16
// baseline (speedup 1.0000x reference)
#include <cuda_runtime.h>
#include <cuda_fp16.h>
#include <cstdint>
#include <cstddef>

#define BB   16
#define LQL  2048
#define LKL  2048
#define DDIM 1024

#define BM 128
#define BN 128
#define NS  3

// ---- QK staging: BK=32 halves (64B rows), 4 tiles per stage ----
#define QK_BK 32
#define QK_TILE_B  8192                      // 128 rows * 64 B
#define QK_STAGE_B (4 * QK_TILE_B)           // Qh,Ql,Kh,Kl
#define QK_SMEM    (NS * QK_STAGE_B)         // 98304 B -> 2 CTAs/SM

// ---- PV staging: BK=64 halves (128B rows, SW128), 2 tiles, 3 stages ----
#define PV_NS 3
#define PV_BK 64
#define PV_TILE_B 16384                      // 128 rows * 128 B
#define PV_STAGE_B (2 * PV_TILE_B)           // 32 KB
#define PV_SMEM (PV_NS * PV_STAGE_B)         // 98304 B -> 2 CTAs/SM

// conversion kernel block split
#define CVT_QK_BLOCKS 32768                  // n4 / 256
#define CVT_V_BLOCKS  (16 * 32 * 32)         // b * ktiles(64) * dtiles(32)

// ---------------- scratch (static device globals; zero-initialized) ----------
__device__ __align__(16) __half g_Qh[(size_t)BB * LQL * DDIM];
__device__ __align__(16) __half g_Ql[(size_t)BB * LQL * DDIM];
__device__ __align__(16) __half g_Kh[(size_t)BB * LKL * DDIM];
__device__ __align__(16) __half g_Kl[(size_t)BB * LKL * DDIM];
__device__ __align__(16) __half g_Vt[(size_t)BB * DDIM * LKL];  // V^T: [b][d][k]
__device__ __align__(16) float  g_S [(size_t)BB * LQL * LKL];
__device__ __align__(16) __half g_P [(size_t)BB * LQL * LKL];

// ---------------- PTX helpers ------------------------------------------------
__device__ __forceinline__ uint32_t s2u(const void* p) {
    return (uint32_t)__cvta_generic_to_shared(p);
}
__device__ __forceinline__ uint32_t sw64(uint32_t o)  { return o ^ ((o >> 3) & 0x30); }
__device__ __forceinline__ uint32_t sw128(uint32_t o) { return o ^ ((o >> 3) & 0x70); }

__device__ __forceinline__ void ldm4(uint32_t* r, uint32_t a) {
    asm volatile("ldmatrix.sync.aligned.m8n8.x4.shared.b16 {%0,%1,%2,%3},[%4];"
                 : "=r"(r[0]), "=r"(r[1]), "=r"(r[2]), "=r"(r[3]) : "r"(a));
}
__device__ __forceinline__ void mma_f16(float* c, const uint32_t* a, uint32_t b0, uint32_t b1) {
    asm volatile("mma.sync.aligned.m16n8k16.row.col.f32.f16.f16.f32 "
                 "{%0,%1,%2,%3},{%4,%5,%6,%7},{%8,%9},{%0,%1,%2,%3};"
                 : "+f"(c[0]), "+f"(c[1]), "+f"(c[2]), "+f"(c[3])
                 : "r"(a[0]), "r"(a[1]), "r"(a[2]), "r"(a[3]), "r"(b0), "r"(b1));
}
__device__ __forceinline__ void cpa16(uint32_t s, const void* g) {
    asm volatile("cp.async.cg.shared.global [%0],[%1],16;" :: "r"(s), "l"(g));
}
__device__ __forceinline__ void cpcommit() { asm volatile("cp.async.commit_group;"); }

// ---------------- merged conversion kernel -----------------------------------
// blocks [0, CVT_QK_BLOCKS): Q,K hi/lo split (K rows masked by key_len)
// blocks [CVT_QK_BLOCKS, +CVT_V_BLOCKS): V transpose (masked by key_len)
__global__ __launch_bounds__(256)
void cvt_all_kernel(const float4* __restrict__ q,
                    const float4* __restrict__ k,
                    const float* __restrict__ v,
                    const int* __restrict__ key_len) {
    __shared__ __half tile[64][33];
    int bx = blockIdx.x;

    if (bx < CVT_QK_BLOCKS) {
        int i = bx * 256 + threadIdx.x;
        {
            float4 x = q[i];
            __half h0 = __float2half_rn(x.x), h1 = __float2half_rn(x.y);
            __half h2 = __float2half_rn(x.z), h3 = __float2half_rn(x.w);
            ((__half2*)g_Qh)[2 * i]     = __halves2half2(h0, h1);
            ((__half2*)g_Qh)[2 * i + 1] = __halves2half2(h2, h3);
            ((__half2*)g_Ql)[2 * i]     = __halves2half2(
                __float2half_rn(x.x - __half2float(h0)), __float2half_rn(x.y - __half2float(h1)));
            ((__half2*)g_Ql)[2 * i + 1] = __halves2half2(
                __float2half_rn(x.z - __half2float(h2)), __float2half_rn(x.w - __half2float(h3)));
        }
        {
            int klb = __ldg(&key_len[i >> 19]);
            int row = (i & 524287) >> 8;
            int kmaxK = ((klb + 127) >> 7) << 7;   // QK reads K rows < ceil(kl/128)*128
            if (row < kmaxK) {
                float4 x = k[i];
                __half h0 = __float2half_rn(x.x), h1 = __float2half_rn(x.y);
                __half h2 = __float2half_rn(x.z), h3 = __float2half_rn(x.w);
                ((__half2*)g_Kh)[2 * i]     = __halves2half2(h0, h1);
                ((__half2*)g_Kh)[2 * i + 1] = __halves2half2(h2, h3);
                ((__half2*)g_Kl)[2 * i]     = __halves2half2(
                    __float2half_rn(x.x - __half2float(h0)), __float2half_rn(x.y - __half2float(h1)));
                ((__half2*)g_Kl)[2 * i + 1] = __halves2half2(
                    __float2half_rn(x.z - __half2float(h2)), __float2half_rn(x.w - __half2float(h3)));
            }
        }
    } else {
        int id = bx - CVT_QK_BLOCKS;
        int b  = id >> 10;
        int rem = id & 1023;
        int k0 = (rem >> 5) * 64;
        int d0 = (rem & 31) * 32;
        int klb = __ldg(&key_len[b]);
        int kmax = (klb == 0) ? LKL : (((klb + 63) >> 6) << 6);
        if (k0 >= kmax) return;

        int x = threadIdx.x & 31, y = threadIdx.x >> 5;   // 32 x 8
        const float* src = v + ((size_t)b * LKL + k0) * DDIM + d0;
#pragma unroll
        for (int i = 0; i < 8; i++)                       // 64 k-rows
            tile[y + 8 * i][x] = __float2half_rn(src[(size_t)(y + 8 * i) * DDIM + x]);
        __syncthreads();
        __half* dst = g_Vt + ((size_t)b * DDIM + d0) * LKL + k0;
#pragma unroll
        for (int i = 0; i < 4; i++) {                     // 32 d-rows, half2 stores
            int d = y + 8 * i;
            __half2 hv = __halves2half2(tile[2 * x][d], tile[2 * x + 1][d]);
            *(__half2*)(dst + (size_t)d * LKL + 2 * x) = hv;
        }
    }
}

// ---- GEMM1: S = Q K^T, fused 3-pass, 4 warps, warp tile 64x64 ---------------
__global__ __launch_bounds__(128, 2)
void gemm_qk_kernel(const int* __restrict__ key_len) {
    int b  = blockIdx.z;
    int kl = key_len[b];
    int n0 = blockIdx.x * BN;
    if (n0 >= kl) return;            // masked tile (also kl==0)
    int m0 = blockIdx.y * BM;

    extern __shared__ __half sm[];
    uint32_t smb = s2u(sm);

    int tid = threadIdx.x;
    const __half* srcQh = g_Qh + ((size_t)b * LQL + m0) * DDIM;
    const __half* srcQl = g_Ql + ((size_t)b * LQL + m0) * DDIM;
    const __half* srcKh = g_Kh + ((size_t)b * LKL + n0) * DDIM;
    const __half* srcKl = g_Kl + ((size_t)b * LKL + n0) * DDIM;

    int lc = tid & 3, lr = tid >> 2;

    auto issue = [&](int t) {
        int k0 = t * QK_BK;
        uint32_t st = smb + (t % NS) * QK_STAGE_B;
        const __half* pQh = srcQh + k0 + lc * 8;
        const __half* pQl = srcQl + k0 + lc * 8;
        const __half* pKh = srcKh + k0 + lc * 8;
        const __half* pKl = srcKl + k0 + lc * 8;
#pragma unroll
        for (int p = 0; p < 4; p++) {
            int row = p * 32 + lr;
            uint32_t so = sw64(row * 64 + lc * 16);
            cpa16(st + so,                 pQh + (size_t)row * DDIM);
            cpa16(st + QK_TILE_B + so,     pQl + (size_t)row * DDIM);
            cpa16(st + 2 * QK_TILE_B + so, pKh + (size_t)row * DDIM);
            cpa16(st + 3 * QK_TILE_B + so, pKl + (size_t)row * DDIM);
        }
        cpcommit();
    };

    float acc[4][8][4];
#pragma unroll
    for (int mt = 0; mt < 4; mt++)
#pragma unroll
        for (int nt = 0; nt < 8; nt++)
#pragma unroll
            for (int j = 0; j < 4; j++) acc[mt][nt][j] = 0.0f;

    int lane = tid & 31, wid = tid >> 5;
    int wm = wid >> 1, wn = wid & 1;              // 2x2 grid, warp tile 64x64
    int arow = lane & 15, ac = lane >> 4;
    int g    = lane >> 3;
    int brow = (lane & 7) + ((g >> 1) << 3);
    int bc   = g & 1;

    const int KT = DDIM / QK_BK;                  // 32
    issue(0);
    issue(1);

    for (int s = 0; s < KT; s++) {
        if (s + 1 < KT) asm volatile("cp.async.wait_group 1;");
        else            asm volatile("cp.async.wait_group 0;");
        __syncthreads();
        if (s + 2 < KT) issue(s + 2);

        uint32_t st = smb + (s % NS) * QK_STAGE_B;
        uint32_t tQh = st, tQl = st + QK_TILE_B;
        uint32_t tKh = st + 2 * QK_TILE_B, tKl = st + 3 * QK_TILE_B;

#pragma unroll
        for (int kk = 0; kk < 2; kk++) {
            uint32_t aQh[4][4], aQl[4][4], bh[8][2], bl[8][2];
#pragma unroll
            for (int nt2 = 0; nt2 < 4; nt2++) {
                uint32_t off = sw64((wn * 64 + nt2 * 16 + brow) * 64 + (kk * 2 + bc) * 16);
                uint32_t r[4];
                ldm4(r, tKh + off);
                bh[nt2 * 2][0] = r[0];     bh[nt2 * 2][1] = r[1];
                bh[nt2 * 2 + 1][0] = r[2]; bh[nt2 * 2 + 1][1] = r[3];
                ldm4(r, tKl + off);
                bl[nt2 * 2][0] = r[0];     bl[nt2 * 2][1] = r[1];
                bl[nt2 * 2 + 1][0] = r[2]; bl[nt2 * 2 + 1][1] = r[3];
            }
#pragma unroll
            for (int mt = 0; mt < 4; mt++) {
                uint32_t off = sw64((wm * 64 + mt * 16 + arow) * 64 + (kk * 2 + ac) * 16);
                ldm4(aQh[mt], tQh + off);
            }
#pragma unroll
            for (int mt = 0; mt < 4; mt++) {
                uint32_t off = sw64((wm * 64 + mt * 16 + arow) * 64 + (kk * 2 + ac) * 16);
                ldm4(aQl[mt], tQl + off);
            }
#pragma unroll
            for (int mt = 0; mt < 4; mt++)
#pragma unroll
                for (int nt = 0; nt < 8; nt++)
                    mma_f16(acc[mt][nt], aQh[mt], bh[nt][0], bh[nt][1]);
#pragma unroll
            for (int mt = 0; mt < 4; mt++)
#pragma unroll
                for (int nt = 0; nt < 8; nt++)
                    mma_f16(acc[mt][nt], aQh[mt], bl[nt][0], bl[nt][1]);
#pragma unroll
            for (int mt = 0; mt < 4; mt++)
#pragma unroll
                for (int nt = 0; nt < 8; nt++)
                    mma_f16(acc[mt][nt], aQl[mt], bh[nt][0], bh[nt][1]);
        }
    }

#pragma unroll
    for (int mt = 0; mt < 4; mt++) {
        int r0 = m0 + wm * 64 + mt * 16 + (lane >> 2);
#pragma unroll
        for (int nt = 0; nt < 8; nt++) {
            int c = n0 + wn * 64 + nt * 8 + (lane & 3) * 2;
            float* p0 = g_S + ((size_t)b * LQL + r0) * LKL + c;
            *(float2*)p0             = make_float2(acc[mt][nt][0], acc[mt][nt][1]);
            *(float2*)(p0 + 8 * LKL) = make_float2(acc[mt][nt][2], acc[mt][nt][3]);
        }
    }
}

// ---------------- row softmax: 128 threads, MLP=4, register-resident ---------
__global__ __launch_bounds__(128)
void softmax_kernel(const int* __restrict__ key_len) {
    int row = blockIdx.x;
    int b = row >> 11;
    int kl = key_len[b];
    __half* prow = g_P + (size_t)row * LKL;
    int tid = threadIdx.x;
    int lane = tid & 31, wid = tid >> 5;

    if (kl == 0) {                   // all masked -> uniform softmax
        __half2 u2 = __halves2half2(__float2half(1.0f / 2048.0f), __float2half(1.0f / 2048.0f));
        __half2* p2 = (__half2*)prow;
        for (int i = tid; i < LKL / 2; i += 128) p2[i] = u2;
        return;
    }

    const float4* s4 = (const float4*)(g_S + (size_t)row * LKL);
    __shared__ float red[4];

    float4 v[4];
    float lmax = -3.4e38f;
#pragma unroll
    for (int j = 0; j < 4; j++) {
        int idx = j * 128 + tid;
        int k0 = idx << 2;
        if (k0 < kl) {
            v[j] = s4[idx];
            if (k0 + 1 >= kl) v[j].y = -3.4e38f;
            if (k0 + 2 >= kl) v[j].z = -3.4e38f;
            if (k0 + 3 >= kl) v[j].w = -3.4e38f;
        } else {
            v[j] = make_float4(-3.4e38f, -3.4e38f, -3.4e38f, -3.4e38f);
        }
    }
#pragma unroll
    for (int j = 0; j < 4; j++)
        lmax = fmaxf(fmaxf(lmax, fmaxf(v[j].x, v[j].y)), fmaxf(v[j].z, v[j].w));
#pragma unroll
    for (int o = 16; o > 0; o >>= 1)
        lmax = fmaxf(lmax, __shfl_xor_sync(0xffffffffu, lmax, o));
    if (lane == 0) red[wid] = lmax;
    __syncthreads();
    float m = fmaxf(fmaxf(red[0], red[1]), fmaxf(red[2], red[3]));
    __syncthreads();

    float lsum = 0.0f;
#pragma unroll
    for (int j = 0; j < 4; j++) {
        v[j].x = __expf(v[j].x - m);
        v[j].y = __expf(v[j].y - m);
        v[j].z = __expf(v[j].z - m);
        v[j].w = __expf(v[j].w - m);
        lsum += (v[j].x + v[j].y) + (v[j].z + v[j].w);
    }
#pragma unroll
    for (int o = 16; o > 0; o >>= 1)
        lsum += __shfl_xor_sync(0xffffffffu, lsum, o);
    if (lane == 0) red[wid] = lsum;
    __syncthreads();
    float inv = 1.0f / (red[0] + red[1] + red[2] + red[3]);

    int kmax = ((kl + 63) >> 6) << 6;
#pragma unroll
    for (int j = 0; j < 4; j++) {
        int idx = j * 128 + tid;
        int k0 = idx << 2;
        if (k0 < kmax) {
            __half2 h0 = __halves2half2(__float2half(v[j].x * inv), __float2half(v[j].y * inv));
            __half2 h1 = __halves2half2(__float2half(v[j].z * inv), __float2half(v[j].w * inv));
            uint2 pack;
            pack.x = *(uint32_t*)&h0;
            pack.y = *(uint32_t*)&h1;
            *(uint2*)(prow + k0) = pack;
        }
    }
}

// ---- GEMM2: O = P V  (BK=64, SW128 rows, normal ldm4 both, NS=3) ------------
__global__ __launch_bounds__(128, 2)
void gemm_pv_kernel(float* __restrict__ out, const int* __restrict__ key_len) {
    int b  = blockIdx.z;
    int kl = key_len[b];
    int n0 = blockIdx.x * BN;        // over D
    int m0 = blockIdx.y * BM;

    extern __shared__ __half sm[];
    uint32_t smb = s2u(sm);
    int tid = threadIdx.x;

    const __half* srcP  = g_P  + ((size_t)b * LQL + m0) * LKL;
    const __half* srcVt = g_Vt + ((size_t)b * DDIM + n0) * LKL;

    int lc = tid & 7, lr = tid >> 3;              // 8 chunks/row, 16 rows/pass

    auto issue = [&](int t) {
        int k0 = t * PV_BK;
        uint32_t st = smb + (t % PV_NS) * PV_STAGE_B;
        const __half* pP = srcP  + k0 + lc * 8;
        const __half* pV = srcVt + k0 + lc * 8;
#pragma unroll
        for (int p = 0; p < 8; p++) {
            int row = p * 16 + lr;
            uint32_t so = sw128(row * 128 + lc * 16);
            cpa16(st + so,             pP + (size_t)row * LKL);
            cpa16(st + PV_TILE_B + so, pV + (size_t)row * LKL);
        }
        cpcommit();
    };

    float acc[4][8][4];
#pragma unroll
    for (int mt = 0; mt < 4; mt++)
#pragma unroll
        for (int nt = 0; nt < 8; nt++)
#pragma unroll
            for (int j = 0; j < 4; j++) acc[mt][nt][j] = 0.0f;

    int lane = tid & 31, wid = tid >> 5;
    int wm = wid >> 1, wn = wid & 1;              // 2x2 grid, warp tile 64x64
    int arow = lane & 15, ac = lane >> 4;
    int g    = lane >> 3;
    int brow = (lane & 7) + ((g >> 1) << 3);
    int bc   = g & 1;

    int KT = (kl == 0) ? (LKL / PV_BK) : ((kl + PV_BK - 1) >> 6);

    issue(0);
    if (KT > 1) issue(1);

    for (int s = 0; s < KT; s++) {
        if (s + 1 < KT) asm volatile("cp.async.wait_group 1;");
        else            asm volatile("cp.async.wait_group 0;");
        __syncthreads();
        if (s + 2 < KT) issue(s + 2);

        uint32_t st = smb + (s % PV_NS) * PV_STAGE_B;
        uint32_t tP = st, tV = st + PV_TILE_B;

#pragma unroll
        for (int kk = 0; kk < 4; kk++) {
            uint32_t a[4][4], bf[8][2];
#pragma unroll
            for (int nt2 = 0; nt2 < 4; nt2++) {
                uint32_t off = sw128((wn * 64 + nt2 * 16 + brow) * 128 + (kk * 2 + bc) * 16);
                uint32_t r[4];
                ldm4(r, tV + off);
                bf[nt2 * 2][0] = r[0];     bf[nt2 * 2][1] = r[1];
                bf[nt2 * 2 + 1][0] = r[2]; bf[nt2 * 2 + 1][1] = r[3];
            }
#pragma unroll
            for (int mt = 0; mt < 4; mt++) {
                uint32_t off = sw128((wm * 64 + mt * 16 + arow) * 128 + (kk * 2 + ac) * 16);
                ldm4(a[mt], tP + off);
            }
#pragma unroll
            for (int mt = 0; mt < 4; mt++)
#pragma unroll
                for (int nt = 0; nt < 8; nt++)
                    mma_f16(acc[mt][nt], a[mt], bf[nt][0], bf[nt][1]);
        }
    }

#pragma unroll
    for (int mt = 0; mt < 4; mt++) {
        int r0 = m0 + wm * 64 + mt * 16 + (lane >> 2);
#pragma unroll
        for (int nt = 0; nt < 8; nt++) {
            int c = n0 + wn * 64 + nt * 8 + (lane & 3) * 2;
            float* p0 = out + ((size_t)b * LQL + r0) * DDIM + c;
            *(float2*)p0              = make_float2(acc[mt][nt][0], acc[mt][nt][1]);
            *(float2*)(p0 + 8 * DDIM) = make_float2(acc[mt][nt][2], acc[mt][nt][3]);
        }
    }
}

// ---------------- launch ------------------------------------------------------
extern "C" void kernel_launch(void* const* d_in, const int* in_sizes, int n_in,
                              void* d_out, int out_size) {
    const float* q  = (const float*)d_in[0];
    const float* k  = (const float*)d_in[1];
    const float* v  = (const float*)d_in[2];
    const int*   kl = (const int*)d_in[3];
    float* out = (float*)d_out;

    cudaFuncSetAttribute(gemm_qk_kernel, cudaFuncAttributeMaxDynamicSharedMemorySize, QK_SMEM);
    cudaFuncSetAttribute(gemm_pv_kernel, cudaFuncAttributeMaxDynamicSharedMemorySize, PV_SMEM);

    cvt_all_kernel<<<CVT_QK_BLOCKS + CVT_V_BLOCKS, 256>>>(
        (const float4*)q, (const float4*)k, v, kl);

    gemm_qk_kernel<<<dim3(LKL / BN, LQL / BM, BB), 128, QK_SMEM>>>(kl);
    softmax_kernel<<<BB * LQL, 128>>>(kl);
    gemm_pv_kernel<<<dim3(DDIM / BN, LQL / BM, BB), 128, PV_SMEM>>>(out, kl);
}

// round 17
// speedup vs baseline: 1.0151x; 1.0151x over previous
#include <cuda_runtime.h>
#include <cuda_fp16.h>
#include <cstdint>
#include <cstddef>

#define BB   16
#define LQL  2048
#define LKL  2048
#define DDIM 1024

#define BM 128
#define BN 128
#define NS  3

// ---- QK staging: BK=32 halves (64B rows), 4 tiles per stage ----
#define QK_BK 32
#define QK_TILE_B  8192                      // 128 rows * 64 B
#define QK_STAGE_B (4 * QK_TILE_B)           // Qh,Ql,Kh,Kl
#define QK_SMEM    (NS * QK_STAGE_B)         // 98304 B -> 2 CTAs/SM

// ---- PV staging: BK=32, 2 tiles (P, Vt) per stage, 5 stages ----
#define PV_NS 5
#define PV_BK 32
#define PV_TILE_B 8192
#define PV_STAGE_B (2 * PV_TILE_B)           // 16 KB
#define PV_SMEM (PV_NS * PV_STAGE_B)         // 81920 B -> 2 CTAs/SM

// conversion kernel block split
#define CVT_QK_BLOCKS 32768                  // n4 / 256
#define CVT_V_BLOCKS  (16 * 32 * 32)         // b * ktiles(64) * dtiles(32)

// ---------------- scratch (static device globals; zero-initialized) ----------
__device__ __align__(16) __half g_Qh[(size_t)BB * LQL * DDIM];
__device__ __align__(16) __half g_Ql[(size_t)BB * LQL * DDIM];
__device__ __align__(16) __half g_Kh[(size_t)BB * LKL * DDIM];
__device__ __align__(16) __half g_Kl[(size_t)BB * LKL * DDIM];
__device__ __align__(16) __half g_Vt[(size_t)BB * DDIM * LKL];  // V^T: [b][d][k]
__device__ __align__(16) float  g_S [(size_t)BB * LQL * LKL];
__device__ __align__(16) __half g_P [(size_t)BB * LQL * LKL];

// ---------------- PTX helpers ------------------------------------------------
__device__ __forceinline__ uint32_t s2u(const void* p) {
    return (uint32_t)__cvta_generic_to_shared(p);
}
__device__ __forceinline__ uint32_t sw64(uint32_t o) { return o ^ ((o >> 3) & 0x30); }

__device__ __forceinline__ void ldm4(uint32_t* r, uint32_t a) {
    asm volatile("ldmatrix.sync.aligned.m8n8.x4.shared.b16 {%0,%1,%2,%3},[%4];"
                 : "=r"(r[0]), "=r"(r[1]), "=r"(r[2]), "=r"(r[3]) : "r"(a));
}
__device__ __forceinline__ void mma_f16(float* c, const uint32_t* a, uint32_t b0, uint32_t b1) {
    asm volatile("mma.sync.aligned.m16n8k16.row.col.f32.f16.f16.f32 "
                 "{%0,%1,%2,%3},{%4,%5,%6,%7},{%8,%9},{%0,%1,%2,%3};"
                 : "+f"(c[0]), "+f"(c[1]), "+f"(c[2]), "+f"(c[3])
                 : "r"(a[0]), "r"(a[1]), "r"(a[2]), "r"(a[3]), "r"(b0), "r"(b1));
}
__device__ __forceinline__ void cpa16(uint32_t s, const void* g) {
    asm volatile("cp.async.cg.shared.global [%0],[%1],16;" :: "r"(s), "l"(g));
}
__device__ __forceinline__ void cpcommit() { asm volatile("cp.async.commit_group;"); }

// ---------------- merged conversion kernel -----------------------------------
// blocks [0, CVT_QK_BLOCKS): Q,K hi/lo split (K rows masked by key_len)
// blocks [CVT_QK_BLOCKS, +CVT_V_BLOCKS): V transpose (masked by key_len)
__global__ __launch_bounds__(256)
void cvt_all_kernel(const float4* __restrict__ q,
                    const float4* __restrict__ k,
                    const float* __restrict__ v,
                    const int* __restrict__ key_len) {
    __shared__ __half tile[64][33];
    int bx = blockIdx.x;

    if (bx < CVT_QK_BLOCKS) {
        int i = bx * 256 + threadIdx.x;
        {
            float4 x = q[i];
            __half h0 = __float2half_rn(x.x), h1 = __float2half_rn(x.y);
            __half h2 = __float2half_rn(x.z), h3 = __float2half_rn(x.w);
            ((__half2*)g_Qh)[2 * i]     = __halves2half2(h0, h1);
            ((__half2*)g_Qh)[2 * i + 1] = __halves2half2(h2, h3);
            ((__half2*)g_Ql)[2 * i]     = __halves2half2(
                __float2half_rn(x.x - __half2float(h0)), __float2half_rn(x.y - __half2float(h1)));
            ((__half2*)g_Ql)[2 * i + 1] = __halves2half2(
                __float2half_rn(x.z - __half2float(h2)), __float2half_rn(x.w - __half2float(h3)));
        }
        {
            int klb = __ldg(&key_len[i >> 19]);
            int row = (i & 524287) >> 8;
            int kmaxK = ((klb + 127) >> 7) << 7;   // QK reads K rows < ceil(kl/128)*128
            if (row < kmaxK) {
                float4 x = k[i];
                __half h0 = __float2half_rn(x.x), h1 = __float2half_rn(x.y);
                __half h2 = __float2half_rn(x.z), h3 = __float2half_rn(x.w);
                ((__half2*)g_Kh)[2 * i]     = __halves2half2(h0, h1);
                ((__half2*)g_Kh)[2 * i + 1] = __halves2half2(h2, h3);
                ((__half2*)g_Kl)[2 * i]     = __halves2half2(
                    __float2half_rn(x.x - __half2float(h0)), __float2half_rn(x.y - __half2float(h1)));
                ((__half2*)g_Kl)[2 * i + 1] = __halves2half2(
                    __float2half_rn(x.z - __half2float(h2)), __float2half_rn(x.w - __half2float(h3)));
            }
        }
    } else {
        int id = bx - CVT_QK_BLOCKS;
        int b  = id >> 10;
        int rem = id & 1023;
        int k0 = (rem >> 5) * 64;
        int d0 = (rem & 31) * 32;
        int klb = __ldg(&key_len[b]);
        int kmax = (klb == 0) ? LKL : (((klb + 63) >> 6) << 6);
        if (k0 >= kmax) return;

        int x = threadIdx.x & 31, y = threadIdx.x >> 5;   // 32 x 8
        const float* src = v + ((size_t)b * LKL + k0) * DDIM + d0;
#pragma unroll
        for (int i = 0; i < 8; i++)                       // 64 k-rows
            tile[y + 8 * i][x] = __float2half_rn(src[(size_t)(y + 8 * i) * DDIM + x]);
        __syncthreads();
        __half* dst = g_Vt + ((size_t)b * DDIM + d0) * LKL + k0;
#pragma unroll
        for (int i = 0; i < 4; i++) {                     // 32 d-rows, half2 stores
            int d = y + 8 * i;
            __half2 hv = __halves2half2(tile[2 * x][d], tile[2 * x + 1][d]);
            *(__half2*)(dst + (size_t)d * LKL + 2 * x) = hv;
        }
    }
}

// ---- GEMM1: S = Q K^T, fused 3-pass, 4 warps, warp tile 64x64 ---------------
__global__ __launch_bounds__(128, 2)
void gemm_qk_kernel(const int* __restrict__ key_len) {
    int b  = blockIdx.z;
    int kl = key_len[b];
    int n0 = blockIdx.x * BN;
    if (n0 >= kl) return;            // masked tile (also kl==0)
    int m0 = blockIdx.y * BM;

    extern __shared__ __half sm[];
    uint32_t smb = s2u(sm);

    int tid = threadIdx.x;
    const __half* srcQh = g_Qh + ((size_t)b * LQL + m0) * DDIM;
    const __half* srcQl = g_Ql + ((size_t)b * LQL + m0) * DDIM;
    const __half* srcKh = g_Kh + ((size_t)b * LKL + n0) * DDIM;
    const __half* srcKl = g_Kl + ((size_t)b * LKL + n0) * DDIM;

    int lc = tid & 3, lr = tid >> 2;

    auto issue = [&](int t) {
        int k0 = t * QK_BK;
        uint32_t st = smb + (t % NS) * QK_STAGE_B;
        const __half* pQh = srcQh + k0 + lc * 8;
        const __half* pQl = srcQl + k0 + lc * 8;
        const __half* pKh = srcKh + k0 + lc * 8;
        const __half* pKl = srcKl + k0 + lc * 8;
#pragma unroll
        for (int p = 0; p < 4; p++) {
            int row = p * 32 + lr;
            uint32_t so = sw64(row * 64 + lc * 16);
            cpa16(st + so,                 pQh + (size_t)row * DDIM);
            cpa16(st + QK_TILE_B + so,     pQl + (size_t)row * DDIM);
            cpa16(st + 2 * QK_TILE_B + so, pKh + (size_t)row * DDIM);
            cpa16(st + 3 * QK_TILE_B + so, pKl + (size_t)row * DDIM);
        }
        cpcommit();
    };

    float acc[4][8][4];
#pragma unroll
    for (int mt = 0; mt < 4; mt++)
#pragma unroll
        for (int nt = 0; nt < 8; nt++)
#pragma unroll
            for (int j = 0; j < 4; j++) acc[mt][nt][j] = 0.0f;

    int lane = tid & 31, wid = tid >> 5;
    int wm = wid >> 1, wn = wid & 1;              // 2x2 grid, warp tile 64x64
    int arow = lane & 15, ac = lane >> 4;
    int g    = lane >> 3;
    int brow = (lane & 7) + ((g >> 1) << 3);
    int bc   = g & 1;

    const int KT = DDIM / QK_BK;                  // 32
    issue(0);
    issue(1);

    for (int s = 0; s < KT; s++) {
        if (s + 1 < KT) asm volatile("cp.async.wait_group 1;");
        else            asm volatile("cp.async.wait_group 0;");
        __syncthreads();
        if (s + 2 < KT) issue(s + 2);

        uint32_t st = smb + (s % NS) * QK_STAGE_B;
        uint32_t tQh = st, tQl = st + QK_TILE_B;
        uint32_t tKh = st + 2 * QK_TILE_B, tKl = st + 3 * QK_TILE_B;

#pragma unroll
        for (int kk = 0; kk < 2; kk++) {
            uint32_t aQh[4][4], aQl[4][4], bh[8][2], bl[8][2];
#pragma unroll
            for (int nt2 = 0; nt2 < 4; nt2++) {
                uint32_t off = sw64((wn * 64 + nt2 * 16 + brow) * 64 + (kk * 2 + bc) * 16);
                uint32_t r[4];
                ldm4(r, tKh + off);
                bh[nt2 * 2][0] = r[0];     bh[nt2 * 2][1] = r[1];
                bh[nt2 * 2 + 1][0] = r[2]; bh[nt2 * 2 + 1][1] = r[3];
                ldm4(r, tKl + off);
                bl[nt2 * 2][0] = r[0];     bl[nt2 * 2][1] = r[1];
                bl[nt2 * 2 + 1][0] = r[2]; bl[nt2 * 2 + 1][1] = r[3];
            }
#pragma unroll
            for (int mt = 0; mt < 4; mt++) {
                uint32_t off = sw64((wm * 64 + mt * 16 + arow) * 64 + (kk * 2 + ac) * 16);
                ldm4(aQh[mt], tQh + off);
            }
#pragma unroll
            for (int mt = 0; mt < 4; mt++) {
                uint32_t off = sw64((wm * 64 + mt * 16 + arow) * 64 + (kk * 2 + ac) * 16);
                ldm4(aQl[mt], tQl + off);
            }
#pragma unroll
            for (int mt = 0; mt < 4; mt++)
#pragma unroll
                for (int nt = 0; nt < 8; nt++)
                    mma_f16(acc[mt][nt], aQh[mt], bh[nt][0], bh[nt][1]);
#pragma unroll
            for (int mt = 0; mt < 4; mt++)
#pragma unroll
                for (int nt = 0; nt < 8; nt++)
                    mma_f16(acc[mt][nt], aQh[mt], bl[nt][0], bl[nt][1]);
#pragma unroll
            for (int mt = 0; mt < 4; mt++)
#pragma unroll
                for (int nt = 0; nt < 8; nt++)
                    mma_f16(acc[mt][nt], aQl[mt], bh[nt][0], bh[nt][1]);
        }
    }

#pragma unroll
    for (int mt = 0; mt < 4; mt++) {
        int r0 = m0 + wm * 64 + mt * 16 + (lane >> 2);
#pragma unroll
        for (int nt = 0; nt < 8; nt++) {
            int c = n0 + wn * 64 + nt * 8 + (lane & 3) * 2;
            float* p0 = g_S + ((size_t)b * LQL + r0) * LKL + c;
            *(float2*)p0             = make_float2(acc[mt][nt][0], acc[mt][nt][1]);
            *(float2*)(p0 + 8 * LKL) = make_float2(acc[mt][nt][2], acc[mt][nt][3]);
        }
    }
}

// ---------------- row softmax: 128 threads, MLP=4, register-resident ---------
__global__ __launch_bounds__(128)
void softmax_kernel(const int* __restrict__ key_len) {
    int row = blockIdx.x;
    int b = row >> 11;
    int kl = key_len[b];
    __half* prow = g_P + (size_t)row * LKL;
    int tid = threadIdx.x;
    int lane = tid & 31, wid = tid >> 5;

    if (kl == 0) {                   // all masked -> uniform softmax
        __half2 u2 = __halves2half2(__float2half(1.0f / 2048.0f), __float2half(1.0f / 2048.0f));
        __half2* p2 = (__half2*)prow;
        for (int i = tid; i < LKL / 2; i += 128) p2[i] = u2;
        return;
    }

    const float4* s4 = (const float4*)(g_S + (size_t)row * LKL);
    __shared__ float red[4];

    // pass 1: 4 independent masked float4 loads per thread (MLP=4), block max
    float4 v[4];
    float lmax = -3.4e38f;
#pragma unroll
    for (int j = 0; j < 4; j++) {
        int idx = j * 128 + tid;
        int k0 = idx << 2;
        if (k0 < kl) {
            v[j] = s4[idx];
            if (k0 + 1 >= kl) v[j].y = -3.4e38f;
            if (k0 + 2 >= kl) v[j].z = -3.4e38f;
            if (k0 + 3 >= kl) v[j].w = -3.4e38f;
        } else {
            v[j] = make_float4(-3.4e38f, -3.4e38f, -3.4e38f, -3.4e38f);
        }
    }
#pragma unroll
    for (int j = 0; j < 4; j++)
        lmax = fmaxf(fmaxf(lmax, fmaxf(v[j].x, v[j].y)), fmaxf(v[j].z, v[j].w));
#pragma unroll
    for (int o = 16; o > 0; o >>= 1)
        lmax = fmaxf(lmax, __shfl_xor_sync(0xffffffffu, lmax, o));
    if (lane == 0) red[wid] = lmax;
    __syncthreads();
    float m = fmaxf(fmaxf(red[0], red[1]), fmaxf(red[2], red[3]));
    __syncthreads();

    // pass 2: exp + block sum
    float lsum = 0.0f;
#pragma unroll
    for (int j = 0; j < 4; j++) {
        v[j].x = __expf(v[j].x - m);
        v[j].y = __expf(v[j].y - m);
        v[j].z = __expf(v[j].z - m);
        v[j].w = __expf(v[j].w - m);
        lsum += (v[j].x + v[j].y) + (v[j].z + v[j].w);
    }
#pragma unroll
    for (int o = 16; o > 0; o >>= 1)
        lsum += __shfl_xor_sync(0xffffffffu, lsum, o);
    if (lane == 0) red[wid] = lsum;
    __syncthreads();
    float inv = 1.0f / (red[0] + red[1] + red[2] + red[3]);

    // pass 3: store fp16 up to ceil(kl/64)*64 (PV reads no further)
    int kmax = ((kl + 63) >> 6) << 6;
#pragma unroll
    for (int j = 0; j < 4; j++) {
        int idx = j * 128 + tid;
        int k0 = idx << 2;
        if (k0 < kmax) {
            __half2 h0 = __halves2half2(__float2half(v[j].x * inv), __float2half(v[j].y * inv));
            __half2 h1 = __halves2half2(__float2half(v[j].z * inv), __float2half(v[j].w * inv));
            uint2 pack;
            pack.x = *(uint32_t*)&h0;
            pack.y = *(uint32_t*)&h1;
            *(uint2*)(prow + k0) = pack;
        }
    }
}

// ---- GEMM2: O = P V  (BK=32, normal ldm4 both operands, NS=5) ---------------
__global__ __launch_bounds__(128, 2)
void gemm_pv_kernel(float* __restrict__ out, const int* __restrict__ key_len) {
    int b  = blockIdx.z;
    int kl = key_len[b];
    int n0 = blockIdx.x * BN;        // over D
    int m0 = blockIdx.y * BM;

    extern __shared__ __half sm[];
    uint32_t smb = s2u(sm);
    int tid = threadIdx.x;

    const __half* srcP  = g_P  + ((size_t)b * LQL + m0) * LKL;
    const __half* srcVt = g_Vt + ((size_t)b * DDIM + n0) * LKL;

    int lc = tid & 3, lr = tid >> 2;

    auto issue = [&](int t) {
        int k0 = t * PV_BK;
        uint32_t st = smb + (t % PV_NS) * PV_STAGE_B;
        const __half* pP = srcP  + k0 + lc * 8;
        const __half* pV = srcVt + k0 + lc * 8;
#pragma unroll
        for (int p = 0; p < 4; p++) {
            int row = p * 32 + lr;
            uint32_t so = sw64(row * 64 + lc * 16);
            cpa16(st + so,             pP + (size_t)row * LKL);
            cpa16(st + PV_TILE_B + so, pV + (size_t)row * LKL);
        }
        cpcommit();
    };

    float acc[4][8][4];
#pragma unroll
    for (int mt = 0; mt < 4; mt++)
#pragma unroll
        for (int nt = 0; nt < 8; nt++)
#pragma unroll
            for (int j = 0; j < 4; j++) acc[mt][nt][j] = 0.0f;

    int lane = tid & 31, wid = tid >> 5;
    int wm = wid >> 1, wn = wid & 1;              // 2x2 grid, warp tile 64x64
    int arow = lane & 15, ac = lane >> 4;
    int g    = lane >> 3;
    int brow = (lane & 7) + ((g >> 1) << 3);
    int bc   = g & 1;

    int KT = (kl == 0) ? (LKL / PV_BK) : ((kl + PV_BK - 1) >> 5);

    issue(0);
    if (KT > 1) issue(1);
    if (KT > 2) issue(2);
    if (KT > 3) issue(3);

    for (int s = 0; s < KT; s++) {
        if (s + 3 < KT)      asm volatile("cp.async.wait_group 3;");
        else if (s + 2 < KT) asm volatile("cp.async.wait_group 2;");
        else if (s + 1 < KT) asm volatile("cp.async.wait_group 1;");
        else                 asm volatile("cp.async.wait_group 0;");
        __syncthreads();
        if (s + 4 < KT) issue(s + 4);

        uint32_t st = smb + (s % PV_NS) * PV_STAGE_B;
        uint32_t tP = st, tV = st + PV_TILE_B;

#pragma unroll
        for (int kk = 0; kk < 2; kk++) {
            uint32_t a[4][4], bf[8][2];
#pragma unroll
            for (int nt2 = 0; nt2 < 4; nt2++) {
                uint32_t off = sw64((wn * 64 + nt2 * 16 + brow) * 64 + (kk * 2 + bc) * 16);
                uint32_t r[4];
                ldm4(r, tV + off);
                bf[nt2 * 2][0] = r[0];     bf[nt2 * 2][1] = r[1];
                bf[nt2 * 2 + 1][0] = r[2]; bf[nt2 * 2 + 1][1] = r[3];
            }
#pragma unroll
            for (int mt = 0; mt < 4; mt++) {
                uint32_t off = sw64((wm * 64 + mt * 16 + arow) * 64 + (kk * 2 + ac) * 16);
                ldm4(a[mt], tP + off);
            }
#pragma unroll
            for (int mt = 0; mt < 4; mt++)
#pragma unroll
                for (int nt = 0; nt < 8; nt++)
                    mma_f16(acc[mt][nt], a[mt], bf[nt][0], bf[nt][1]);
        }
    }

#pragma unroll
    for (int mt = 0; mt < 4; mt++) {
        int r0 = m0 + wm * 64 + mt * 16 + (lane >> 2);
#pragma unroll
        for (int nt = 0; nt < 8; nt++) {
            int c = n0 + wn * 64 + nt * 8 + (lane & 3) * 2;
            float* p0 = out + ((size_t)b * LQL + r0) * DDIM + c;
            *(float2*)p0              = make_float2(acc[mt][nt][0], acc[mt][nt][1]);
            *(float2*)(p0 + 8 * DDIM) = make_float2(acc[mt][nt][2], acc[mt][nt][3]);
        }
    }
}

// ---------------- launch ------------------------------------------------------
extern "C" void kernel_launch(void* const* d_in, const int* in_sizes, int n_in,
                              void* d_out, int out_size) {
    const float* q  = (const float*)d_in[0];
    const float* k  = (const float*)d_in[1];
    const float* v  = (const float*)d_in[2];
    const int*   kl = (const int*)d_in[3];
    float* out = (float*)d_out;

    cudaFuncSetAttribute(gemm_qk_kernel, cudaFuncAttributeMaxDynamicSharedMemorySize, QK_SMEM);
    cudaFuncSetAttribute(gemm_pv_kernel, cudaFuncAttributeMaxDynamicSharedMemorySize, PV_SMEM);

    cvt_all_kernel<<<CVT_QK_BLOCKS + CVT_V_BLOCKS, 256>>>(
        (const float4*)q, (const float4*)k, v, kl);

    gemm_qk_kernel<<<dim3(LKL / BN, LQL / BM, BB), 128, QK_SMEM>>>(kl);
    softmax_kernel<<<BB * LQL, 128>>>(kl);
    gemm_pv_kernel<<<dim3(DDIM / BN, LQL / BM, BB), 128, PV_SMEM>>>(out, kl);
}